// round 7
// baseline (speedup 1.0000x reference)
#include <cuda_runtime.h>

// Fused shift + grouped conv(H taps, w1) + grouped conv(W taps, w2).
//
// x:  (1,512,14,14) fp32, channel c = i*8 + o   (i=0..63, o=0..7)
// Stage 1: y[k,o,h,w] = sum_{i,j} x[(h+j-2) mod 14][..] * w1[k,i,j],
//          tap j contributes iff 0 <= h+j-1 < 14 (roll +1 along H, zero-pad).
//          Loads always issued (mod-14 row in-bounds); invalid taps are
//          neutralized by zeroing the CTA-uniform weight.
// Stage 2: out[(i2*16+k)*196 + h*14 + w] = sum_{o,t} y[k,o,h,w-1+t] * w2[i2,o,t]
//
// Grid (8 k-pairs, 14 h) = 112 CTAs, 448 threads. Each CTA computes TWO k
// values from ONE set of x loads (halves chip x-traffic and per-SM L1tex
// wavefronts vs one-k-per-CTA).
// Stage-1 thread = (g 0..7 splits i, o 0..7, wp 0..6 -> w-pair), 4 accums.
// Stage-2 thread = (i2 0..31, kl 0..1, wp 0..6) -> all 448 threads.

__device__ __forceinline__ float2 ldg64v(const float2* p) {
    float2 v;
    asm volatile("ld.global.nc.v2.f32 {%0,%1},[%2];"
                 : "=f"(v.x), "=f"(v.y) : "l"(p));
    return v;
}

__global__ void __launch_bounds__(448, 1) fused_kernel(
    const float* __restrict__ x,
    const float* __restrict__ w1,
    const float* __restrict__ w2,
    float* __restrict__ out)
{
    __shared__ float ws1[384];                 // [kl][i][j], this CTA's k-pair
    __shared__ float ws2[768];                 // all of w2
    __shared__ float part[8 * 2 * 8 * 16];     // [g][kl][o][w pad 16]
    __shared__ float ys[2 * 8 * 16];           // [kl][o][w pad 16]

    const int kp  = blockIdx.x;   // 0..7   (k-pair: k = kp*2 + kl)
    const int h   = blockIdx.y;   // 0..13
    const int tid = threadIdx.x;  // 0..447

    // ---- stage-1 thread decode ----
    const int g   = tid / 56;          // 0..7  (i-split)
    const int rem = tid - g * 56;
    const int o   = rem / 7;           // 0..7
    const int wp  = rem - o * 7;       // 0..6  -> w0 = 2*wp
    const int w0  = wp * 2;

    // taps: source rows (mod-14 roll); always in-bounds
    const int  r0 = (h + 12) % 14;     // j=0, contributes iff h >= 1
    const int  r1 = (h + 13) % 14;     // j=1, always
    const int  r2 = h;                 // j=2, contributes iff h <= 12
    const bool v0 = (h >= 1);
    const bool v2 = (h <= 12);

    const float2* __restrict__ px = (const float2*)x;
    // float2 index of x[(i*8+o)*196 + r*14 + w0] = (i*8+o)*98 + r*7 + wp
    const int e0 = o * 98 + r0 * 7 + wp;
    const int e1 = o * 98 + r1 * 7 + wp;
    const int e2 = o * 98 + r2 * 7 + wp;
    const int ib = g * 8;

    // ---- front-batch all 24 x loads (volatile: cannot sink past barrier) ----
    float2 xv0[8], xv1[8], xv2[8];
    #pragma unroll
    for (int ii = 0; ii < 8; ii++) {
        const int off = (ib + ii) * 784;   // i*8*98
        xv0[ii] = ldg64v(px + off + e0);
        xv1[ii] = ldg64v(px + off + e1);
        xv2[ii] = ldg64v(px + off + e2);
    }

    // ---- weight staging (latency overlaps the x loads above) ----
    if (tid < 384) ws1[tid] = __ldg(w1 + kp * 384 + tid);
    for (int idx = tid; idx < 768; idx += 448) ws2[idx] = __ldg(w2 + idx);

    __syncthreads();   // ws1/ws2 visible; x loads in flight behind it

    // ---- stage 1 FMAs: 2 k x 2 w accumulators off the same x registers ----
    float a0A = 0.f, a0B = 0.f;        // kl=0: w0, w0+1
    float a1A = 0.f, a1B = 0.f;        // kl=1: w0, w0+1
    #pragma unroll
    for (int ii = 0; ii < 8; ii++) {
        const int i = ib + ii;
        const float wa0 = v0 ? ws1[i * 3 + 0] : 0.f;
        const float wb0 =      ws1[i * 3 + 1];
        const float wc0 = v2 ? ws1[i * 3 + 2] : 0.f;
        const float wa1 = v0 ? ws1[192 + i * 3 + 0] : 0.f;
        const float wb1 =      ws1[192 + i * 3 + 1];
        const float wc1 = v2 ? ws1[192 + i * 3 + 2] : 0.f;
        a0A = fmaf(xv0[ii].x, wa0, a0A);
        a0A = fmaf(xv1[ii].x, wb0, a0A);
        a0A = fmaf(xv2[ii].x, wc0, a0A);
        a0B = fmaf(xv0[ii].y, wa0, a0B);
        a0B = fmaf(xv1[ii].y, wb0, a0B);
        a0B = fmaf(xv2[ii].y, wc0, a0B);
        a1A = fmaf(xv0[ii].x, wa1, a1A);
        a1A = fmaf(xv1[ii].x, wb1, a1A);
        a1A = fmaf(xv2[ii].x, wc1, a1A);
        a1B = fmaf(xv0[ii].y, wa1, a1B);
        a1B = fmaf(xv1[ii].y, wb1, a1B);
        a1B = fmaf(xv2[ii].y, wc1, a1B);
    }
    {
        float2* pp = (float2*)part;
        // part[g][kl][o][w16]: float2 index = (g*256 + kl*128 + o*16 + w0)/2
        pp[(g * 256 + o * 16 + w0) >> 1]       = make_float2(a0A, a0B);
        pp[(g * 256 + 128 + o * 16 + w0) >> 1] = make_float2(a1A, a1B);
    }
    __syncthreads();

    // ---- reduce the 8 i-partials per (kl,o,w): 224 threads ----
    if (tid < 224) {
        const int kl  = tid / 112;
        const int r2d = tid - kl * 112;
        const int oo  = r2d / 14;
        const int ww  = r2d - oo * 14;
        const int b   = kl * 128 + oo * 16 + ww;
        float s0 = part[0 * 256 + b] + part[1 * 256 + b];
        float s1 = part[2 * 256 + b] + part[3 * 256 + b];
        float s2 = part[4 * 256 + b] + part[5 * 256 + b];
        float s3 = part[6 * 256 + b] + part[7 * 256 + b];
        ys[b] = (s0 + s1) + (s2 + s3);
    }
    __syncthreads();

    // ---- stage 2: thread = (i2, kl, wp), two w outputs; all 448 threads ----
    {
        const int i2  = tid / 14;          // 0..31
        const int r2d = tid - i2 * 14;
        const int kl  = r2d / 7;           // 0..1
        const int wp2 = r2d - kl * 7;      // 0..6
        const int u0  = wp2 * 2;           // w = u0, u0+1
        const float* yk = ys + kl * 128;

        float acc0 = 0.f, acc1 = 0.f;
        #pragma unroll
        for (int oo = 0; oo < 8; oo++) {
            const float ym1 = (u0 > 0)  ? yk[oo * 16 + u0 - 1] : 0.f;
            const float yc0 =             yk[oo * 16 + u0];
            const float yc1 =             yk[oo * 16 + u0 + 1];
            const float yp2 = (u0 < 12) ? yk[oo * 16 + u0 + 2] : 0.f;
            const float wa = ws2[(i2 * 8 + oo) * 3 + 0];
            const float wb = ws2[(i2 * 8 + oo) * 3 + 1];
            const float wc = ws2[(i2 * 8 + oo) * 3 + 2];
            acc0 = fmaf(ym1, wa, acc0);
            acc0 = fmaf(yc0, wb, acc0);
            acc0 = fmaf(yc1, wc, acc0);
            acc1 = fmaf(yc0, wa, acc1);
            acc1 = fmaf(yc1, wb, acc1);
            acc1 = fmaf(yp2, wc, acc1);
        }

        float2* po = (float2*)(out + (i2 * 16 + kp * 2 + kl) * 196 + h * 14 + u0);
        *po = make_float2(acc0, acc1);
    }
}

extern "C" void kernel_launch(void* const* d_in, const int* in_sizes, int n_in,
                              void* d_out, int out_size)
{
    const float* x  = (const float*)d_in[0];   // (1,512,14,14)
    const float* w1 = (const float*)d_in[1];   // (16,64,3)
    const float* w2 = (const float*)d_in[2];   // (32,8,3)
    float* out = (float*)d_out;                // (1,512,14,14)

    fused_kernel<<<dim3(8, 14), 448>>>(x, w1, w2, out);
}

// round 8
// speedup vs baseline: 1.0037x; 1.0037x over previous
#include <cuda_runtime.h>

// Fused shift + grouped conv(H taps, w1) + grouped conv(W taps, w2).
//
// x:  (1,512,14,14) fp32, channel c = i*8 + o   (i=0..63, o=0..7)
// Stage 1: y[k,o,h,w] = sum_{i,j} x[(h+j-2) mod 14][..] * w1[k,i,j],
//          tap j contributes iff 0 <= h+j-1 < 14 (roll +1 along H, zero-pad).
//          Loads always issued (mod-14 row in-bounds); invalid taps
//          neutralized by zeroing the CTA-uniform weight.
// Stage 2: out[(i2*16+k)*196 + h*14 + w] = sum_{o,t} y[k,o,h,w-1+t] * w2[i2,o,t]
//
// Grid (8 k-pairs, 14 h) = 112 CTAs, 896 threads (28 warps).
// Stage-1 thread = (g 0..15 splits i 16-ways, o 0..7, wp 0..6 -> w-pair),
// 4 accumulators (2 k x 2 w) off 12 front-batched loads.
// Stage-2 thread = (i2 0..31, kl 0..1, wp 0..6) on threads < 448.

__device__ __forceinline__ float2 ldg64v(const float2* p) {
    float2 v;
    asm volatile("ld.global.nc.v2.f32 {%0,%1},[%2];"
                 : "=f"(v.x), "=f"(v.y) : "l"(p));
    return v;
}

__global__ void __launch_bounds__(896, 1) fused_kernel(
    const float* __restrict__ x,
    const float* __restrict__ w1,
    const float* __restrict__ w2,
    float* __restrict__ out)
{
    __shared__ float ws1[384];                  // [kl][i][j], this CTA's k-pair
    __shared__ float ws2[768];                  // all of w2
    __shared__ float part[16 * 2 * 8 * 16];     // [g][kl][o][w pad 16]
    __shared__ float ys[2 * 8 * 16];            // [kl][o][w pad 16]

    const int kp  = blockIdx.x;   // 0..7   (k = kp*2 + kl)
    const int h   = blockIdx.y;   // 0..13
    const int tid = threadIdx.x;  // 0..895

    // ---- stage-1 thread decode ----
    const int g   = tid / 56;          // 0..15 (i-split)
    const int rem = tid - g * 56;
    const int o   = rem / 7;           // 0..7
    const int wp  = rem - o * 7;       // 0..6  -> w0 = 2*wp
    const int w0  = wp * 2;

    // taps: source rows (mod-14 roll); always in-bounds
    const int  r0 = (h + 12) % 14;     // j=0, contributes iff h >= 1
    const int  r1 = (h + 13) % 14;     // j=1, always
    const int  r2 = h;                 // j=2, contributes iff h <= 12
    const bool v0 = (h >= 1);
    const bool v2 = (h <= 12);

    const float2* __restrict__ px = (const float2*)x;
    // float2 index of x[(i*8+o)*196 + r*14 + w0] = (i*8+o)*98 + r*7 + wp
    const int e0 = o * 98 + r0 * 7 + wp;
    const int e1 = o * 98 + r1 * 7 + wp;
    const int e2 = o * 98 + r2 * 7 + wp;
    const int ib = g * 4;

    // ---- front-batch all 12 x loads (volatile: cannot sink past barrier) ----
    float2 xv0[4], xv1[4], xv2[4];
    #pragma unroll
    for (int ii = 0; ii < 4; ii++) {
        const int off = (ib + ii) * 784;   // i*8*98
        xv0[ii] = ldg64v(px + off + e0);
        xv1[ii] = ldg64v(px + off + e1);
        xv2[ii] = ldg64v(px + off + e2);
    }

    // ---- weight staging (latency overlaps the x loads above) ----
    if (tid < 384) ws1[tid] = __ldg(w1 + kp * 384 + tid);
    if (tid < 768) ws2[tid] = __ldg(w2 + tid);

    __syncthreads();   // ws1/ws2 visible; x loads in flight behind it

    // ---- stage 1 FMAs: 2 k x 2 w accumulators off the same x registers ----
    float a0A = 0.f, a0B = 0.f;        // kl=0: w0, w0+1
    float a1A = 0.f, a1B = 0.f;        // kl=1: w0, w0+1
    #pragma unroll
    for (int ii = 0; ii < 4; ii++) {
        const int i = ib + ii;
        const float wa0 = v0 ? ws1[i * 3 + 0] : 0.f;
        const float wb0 =      ws1[i * 3 + 1];
        const float wc0 = v2 ? ws1[i * 3 + 2] : 0.f;
        const float wa1 = v0 ? ws1[192 + i * 3 + 0] : 0.f;
        const float wb1 =      ws1[192 + i * 3 + 1];
        const float wc1 = v2 ? ws1[192 + i * 3 + 2] : 0.f;
        a0A = fmaf(xv0[ii].x, wa0, a0A);
        a0A = fmaf(xv1[ii].x, wb0, a0A);
        a0A = fmaf(xv2[ii].x, wc0, a0A);
        a0B = fmaf(xv0[ii].y, wa0, a0B);
        a0B = fmaf(xv1[ii].y, wb0, a0B);
        a0B = fmaf(xv2[ii].y, wc0, a0B);
        a1A = fmaf(xv0[ii].x, wa1, a1A);
        a1A = fmaf(xv1[ii].x, wb1, a1A);
        a1A = fmaf(xv2[ii].x, wc1, a1A);
        a1B = fmaf(xv0[ii].y, wa1, a1B);
        a1B = fmaf(xv1[ii].y, wb1, a1B);
        a1B = fmaf(xv2[ii].y, wc1, a1B);
    }
    {
        float2* pp = (float2*)part;
        // part[g][kl][o][w16]: float2 index = (g*256 + kl*128 + o*16 + w0)/2
        pp[(g * 256 + o * 16 + w0) >> 1]       = make_float2(a0A, a0B);
        pp[(g * 256 + 128 + o * 16 + w0) >> 1] = make_float2(a1A, a1B);
    }
    __syncthreads();

    // ---- reduce the 16 i-partials per (kl,o,w): 224 threads ----
    if (tid < 224) {
        const int kl  = tid / 112;
        const int r2d = tid - kl * 112;
        const int oo  = r2d / 14;
        const int ww  = r2d - oo * 14;
        const int b   = kl * 128 + oo * 16 + ww;
        float s0 = 0.f, s1 = 0.f, s2 = 0.f, s3 = 0.f;
        #pragma unroll
        for (int gg = 0; gg < 4; gg++) {
            s0 += part[(gg)      * 256 + b];
            s1 += part[(gg + 4)  * 256 + b];
            s2 += part[(gg + 8)  * 256 + b];
            s3 += part[(gg + 12) * 256 + b];
        }
        ys[b] = (s0 + s1) + (s2 + s3);
    }
    __syncthreads();

    // ---- stage 2: thread = (i2, kl, wp), two w outputs; threads < 448 ----
    if (tid < 448) {
        const int i2  = tid / 14;          // 0..31
        const int r2d = tid - i2 * 14;
        const int kl  = r2d / 7;           // 0..1
        const int wp2 = r2d - kl * 7;      // 0..6
        const int u0  = wp2 * 2;           // w = u0, u0+1
        const float* yk = ys + kl * 128;

        float acc0 = 0.f, acc1 = 0.f;
        #pragma unroll
        for (int oo = 0; oo < 8; oo++) {
            const float ym1 = (u0 > 0)  ? yk[oo * 16 + u0 - 1] : 0.f;
            const float yc0 =             yk[oo * 16 + u0];
            const float yc1 =             yk[oo * 16 + u0 + 1];
            const float yp2 = (u0 < 12) ? yk[oo * 16 + u0 + 2] : 0.f;
            const float wa = ws2[(i2 * 8 + oo) * 3 + 0];
            const float wb = ws2[(i2 * 8 + oo) * 3 + 1];
            const float wc = ws2[(i2 * 8 + oo) * 3 + 2];
            acc0 = fmaf(ym1, wa, acc0);
            acc0 = fmaf(yc0, wb, acc0);
            acc0 = fmaf(yc1, wc, acc0);
            acc1 = fmaf(yc0, wa, acc1);
            acc1 = fmaf(yc1, wb, acc1);
            acc1 = fmaf(yp2, wc, acc1);
        }

        float2* po = (float2*)(out + (i2 * 16 + kp * 2 + kl) * 196 + h * 14 + u0);
        *po = make_float2(acc0, acc1);
    }
}

extern "C" void kernel_launch(void* const* d_in, const int* in_sizes, int n_in,
                              void* d_out, int out_size)
{
    const float* x  = (const float*)d_in[0];   // (1,512,14,14)
    const float* w1 = (const float*)d_in[1];   // (16,64,3)
    const float* w2 = (const float*)d_in[2];   // (32,8,3)
    float* out = (float*)d_out;                // (1,512,14,14)

    fused_kernel<<<dim3(8, 14), 896>>>(x, w1, w2, out);
}